// round 2
// baseline (speedup 1.0000x reference)
#include <cuda_runtime.h>

#define EPS 1e-5f

static constexpr int D    = 512;
static constexpr int COLS = 1024;   // 2*D and H (both 1024)
static constexpr int B    = 256;
static constexpr int OUTC = 250;

// ---------------- scratch (device globals; no allocation allowed) ----------------
__device__ float g_gate[100352];
__device__ int   g_segoff[257];
__device__ float g_pooled[B * D];
__device__ float g_pn[B * D];
__device__ float g_z[B * COLS];

// =====================================================================
// Fused GEMM (+bias) -> LayerNorm -> ReLU -> (MODE 0: dot with W2 -> g_gate,
//                                            MODE 1: store -> g_z)
// A is [M, 512] row-major, W is [1024, 512] row-major (we compute A @ W^T).
// =====================================================================
template<int MODE, int BM>
__global__ __launch_bounds__(256) void gemm_ln_kernel(
    const float* __restrict__ A, const float* __restrict__ W,
    const float* __restrict__ bias, const float* __restrict__ lng,
    const float* __restrict__ lnb, const float* __restrict__ W2,
    const float* __restrict__ b2, int M)
{
    constexpr int K  = 512;
    constexpr int BK = 32;
    constexpr int BN = 128;
    constexpr int TM = BM / 8;      // rows per thread (ty in 0..7)

    extern __shared__ float smem[];
    float* sx = smem;                 // [BM][K]
    float* sy = sx + BM * K;          // [BM][COLS]
    float* sw = sy + BM * COLS;       // [BK][BN] (transposed W chunk, swizzled)

    const int tid  = threadIdx.x;
    const int row0 = blockIdx.x * BM;
    const float* Ap = (MODE == 0) ? A : (const float*)g_pn;

    // ---- load x tile (BM*K floats) ----
    {
        const float4* src = (const float4*)Ap;
        float4* dst = (float4*)sx;
        const int nf4  = BM * K / 4;
        const int base = row0 * (K / 4);
        for (int i = tid; i < nf4; i += 256) dst[i] = src[base + i];
    }

    const int tx = tid & 31;   // 32 col-groups of 4 cols = 128 cols
    const int ty = tid >> 5;   // 8 row-groups of TM rows

    // ---- GEMM over 8 column chunks of 128 ----
    for (int cb = 0; cb < COLS; cb += BN) {
        float acc[TM][4];
        #pragma unroll
        for (int i = 0; i < TM; ++i) {
            #pragma unroll
            for (int j = 0; j < 4; ++j) acc[i][j] = 0.f;
        }

        for (int k0 = 0; k0 < K; k0 += BK) {
            __syncthreads();
            // stage W chunk transposed: logical sw[k][col], k in [0,32), col in [0,128)
            // XOR swizzle on 4-col groups by (k>>2): conflict-free stores AND reads.
            #pragma unroll
            for (int it = 0; it < 4; ++it) {
                int f   = tid + 256 * it;     // 0..1023 float4s
                int col = f >> 3;             // 0..127
                int kq  = f & 7;              // k-quad 0..7 (k = 4*kq + j)
                float4 v = *(const float4*)(W + (size_t)(cb + col) * K + k0 + 4 * kq);
                int p = (((col >> 2) ^ kq) << 2) + (col & 3);   // swizzled in-row pos
                sw[(4 * kq + 0) * BN + p] = v.x;
                sw[(4 * kq + 1) * BN + p] = v.y;
                sw[(4 * kq + 2) * BN + p] = v.z;
                sw[(4 * kq + 3) * BN + p] = v.w;
            }
            __syncthreads();

            const float4* swv = (const float4*)sw;
            #pragma unroll
            for (int kq = 0; kq < BK / 4; ++kq) {
                float4 a[TM];
                #pragma unroll
                for (int i = 0; i < TM; ++i)
                    a[i] = *(const float4*)(sx + (TM * ty + i) * K + k0 + 4 * kq);
                #pragma unroll
                for (int kk = 0; kk < 4; ++kk) {
                    float4 bv = swv[(4 * kq + kk) * (BN / 4) + (tx ^ kq)];
                    #pragma unroll
                    for (int i = 0; i < TM; ++i) {
                        float av = (kk == 0) ? a[i].x : (kk == 1) ? a[i].y
                                 : (kk == 2) ? a[i].z : a[i].w;
                        acc[i][0] += av * bv.x;
                        acc[i][1] += av * bv.y;
                        acc[i][2] += av * bv.z;
                        acc[i][3] += av * bv.w;
                    }
                }
            }
        }

        // write chunk (+bias) into sy
        float4 bb = *(const float4*)(bias + cb + 4 * tx);
        #pragma unroll
        for (int i = 0; i < TM; ++i) {
            float4 o;
            o.x = acc[i][0] + bb.x; o.y = acc[i][1] + bb.y;
            o.z = acc[i][2] + bb.z; o.w = acc[i][3] + bb.w;
            *(float4*)(sy + (TM * ty + i) * COLS + cb + 4 * tx) = o;
        }
    }
    __syncthreads();

    // ---- LayerNorm + ReLU (+ gate dot) ; one warp per row ----
    const int lane = tid & 31, warp = tid >> 5;
    for (int r = warp; r < BM; r += 8) {
        const float* yr = sy + r * COLS;
        float s1 = 0.f, s2 = 0.f;
        for (int c = lane; c < COLS; c += 32) { float v = yr[c]; s1 += v; s2 += v * v; }
        #pragma unroll
        for (int o = 16; o > 0; o >>= 1) {
            s1 += __shfl_xor_sync(0xffffffffu, s1, o);
            s2 += __shfl_xor_sync(0xffffffffu, s2, o);
        }
        float mean = s1 * (1.f / COLS);
        float var  = fmaxf(s2 * (1.f / COLS) - mean * mean, 0.f);
        float rstd = rsqrtf(var + EPS);
        if constexpr (MODE == 0) {
            float gsum = 0.f;
            for (int c = lane; c < COLS; c += 32) {
                float v = (yr[c] - mean) * rstd * lng[c] + lnb[c];
                gsum += fmaxf(v, 0.f) * W2[c];
            }
            #pragma unroll
            for (int o = 16; o > 0; o >>= 1)
                gsum += __shfl_xor_sync(0xffffffffu, gsum, o);
            if (lane == 0) g_gate[row0 + r] = gsum + b2[0];
        } else {
            for (int c = lane; c < COLS; c += 32) {
                float v = (yr[c] - mean) * rstd * lng[c] + lnb[c];
                g_z[(size_t)(row0 + r) * COLS + c] = fmaxf(v, 0.f);
            }
        }
    }
}

// =====================================================================
// Segment offsets via binary search (batch_ids sorted ascending)
// =====================================================================
__global__ void segoff_kernel(const int* __restrict__ ids, int N)
{
    int b = threadIdx.x;
    if (b > B) return;
    int lo = 0, hi = N;
    while (lo < hi) { int mid = (lo + hi) >> 1; if (ids[mid] < b) lo = mid + 1; else hi = mid; }
    g_segoff[b] = lo;
}

// =====================================================================
// Per-segment softmax + weighted pooling: g_pooled[b][:] = sum_i w_i * x[i][:]
// =====================================================================
__global__ __launch_bounds__(256) void segpool_kernel(const float* __restrict__ x, int N)
{
    __shared__ float red[32];
    __shared__ float sm_w[256];
    __shared__ float s_m, s_inv;

    const int b = blockIdx.x;
    const int tid = threadIdx.x;
    const int lane = tid & 31, warp = tid >> 5;
    const int s = g_segoff[b], e = g_segoff[b + 1];

    // ---- segment max ----
    float m = -3.402823466e38f;
    for (int i = s + tid; i < e; i += 256) m = fmaxf(m, g_gate[i]);
    #pragma unroll
    for (int o = 16; o > 0; o >>= 1) m = fmaxf(m, __shfl_xor_sync(0xffffffffu, m, o));
    if (lane == 0) red[warp] = m;
    __syncthreads();
    if (tid < 32) {
        float v = (tid < 8) ? red[tid] : -3.402823466e38f;
        #pragma unroll
        for (int o = 4; o > 0; o >>= 1) v = fmaxf(v, __shfl_xor_sync(0xffffffffu, v, o));
        if (tid == 0) s_m = v;
    }
    __syncthreads();
    m = s_m;

    // ---- sum of exp ----
    float ssum = 0.f;
    for (int i = s + tid; i < e; i += 256) ssum += expf(g_gate[i] - m);
    #pragma unroll
    for (int o = 16; o > 0; o >>= 1) ssum += __shfl_xor_sync(0xffffffffu, ssum, o);
    __syncthreads();
    if (lane == 0) red[warp] = ssum;
    __syncthreads();
    if (tid < 32) {
        float v = (tid < 8) ? red[tid] : 0.f;
        #pragma unroll
        for (int o = 4; o > 0; o >>= 1) v += __shfl_xor_sync(0xffffffffu, v, o);
        if (tid == 0) s_inv = (v > 0.f) ? (1.f / v) : 0.f;
    }
    __syncthreads();
    const float inv = s_inv;

    // ---- pooled: each thread owns 2 columns ----
    float2 accp = make_float2(0.f, 0.f);
    for (int base = s; base < e; base += 256) {
        int i = base + tid;
        sm_w[tid] = (i < e) ? expf(g_gate[i] - m) * inv : 0.f;
        __syncthreads();
        int cnt = min(256, e - base);
        #pragma unroll 4
        for (int r = 0; r < cnt; ++r) {
            float w = sm_w[r];
            float2 xv = *(const float2*)(x + (size_t)(base + r) * D + 2 * tid);
            accp.x += w * xv.x;
            accp.y += w * xv.y;
        }
        __syncthreads();
    }
    *(float2*)(g_pooled + b * D + 2 * tid) = accp;
}

// =====================================================================
// LayerNorm on pooled rows -> g_pn
// =====================================================================
__global__ __launch_bounds__(256) void poolln_kernel(const float* __restrict__ g,
                                                     const float* __restrict__ bt)
{
    __shared__ float red[64];
    __shared__ float s_mean, s_rstd;
    const int b = blockIdx.x, tid = threadIdx.x;
    const int lane = tid & 31, warp = tid >> 5;

    float v0 = g_pooled[b * D + tid];
    float v1 = g_pooled[b * D + 256 + tid];
    float s1 = v0 + v1, s2 = v0 * v0 + v1 * v1;
    #pragma unroll
    for (int o = 16; o > 0; o >>= 1) {
        s1 += __shfl_xor_sync(0xffffffffu, s1, o);
        s2 += __shfl_xor_sync(0xffffffffu, s2, o);
    }
    if (lane == 0) { red[warp] = s1; red[8 + warp] = s2; }
    __syncthreads();
    if (tid < 32) {
        float a1 = (tid < 8) ? red[tid] : 0.f;
        float a2 = (tid < 8) ? red[8 + tid] : 0.f;
        #pragma unroll
        for (int o = 4; o > 0; o >>= 1) {
            a1 += __shfl_xor_sync(0xffffffffu, a1, o);
            a2 += __shfl_xor_sync(0xffffffffu, a2, o);
        }
        if (tid == 0) {
            float mean = a1 * (1.f / D);
            float var  = fmaxf(a2 * (1.f / D) - mean * mean, 0.f);
            s_mean = mean;
            s_rstd = rsqrtf(var + EPS);
        }
    }
    __syncthreads();
    float mean = s_mean, rstd = s_rstd;
    g_pn[b * D + tid]       = (v0 - mean) * rstd * g[tid]       + bt[tid];
    g_pn[b * D + 256 + tid] = (v1 - mean) * rstd * g[tid + 256] + bt[tid + 256];
}

// =====================================================================
// logits = z @ mW2^T + mb2   (one CTA per batch row, z row cached in smem)
// =====================================================================
__global__ __launch_bounds__(256) void logits_kernel(const float* __restrict__ W2,
                                                     const float* __restrict__ b2,
                                                     float* __restrict__ out)
{
    __shared__ float sz[COLS];
    const int b = blockIdx.x, tid = threadIdx.x;
    for (int i = tid; i < COLS; i += 256) sz[i] = g_z[(size_t)b * COLS + i];
    __syncthreads();
    if (tid < OUTC) {
        const float4* wr = (const float4*)(W2 + (size_t)tid * COLS);
        const float4* zr = (const float4*)sz;
        float acc = 0.f;
        #pragma unroll 4
        for (int k = 0; k < COLS / 4; ++k) {
            float4 w = wr[k], zz = zr[k];
            acc += w.x * zz.x + w.y * zz.y + w.z * zz.z + w.w * zz.w;
        }
        out[b * OUTC + tid] = acc + b2[tid];
    }
}

// =====================================================================
extern "C" void kernel_launch(void* const* d_in, const int* in_sizes, int n_in,
                              void* d_out, int out_size)
{
    const float* x    = (const float*)d_in[0];
    const int*   ids  = (const int*)  d_in[1];
    const float* gW1  = (const float*)d_in[2];
    const float* gb1  = (const float*)d_in[3];
    const float* glng = (const float*)d_in[4];
    const float* glnb = (const float*)d_in[5];
    const float* gW2  = (const float*)d_in[6];
    const float* gb2  = (const float*)d_in[7];
    const float* png  = (const float*)d_in[8];
    const float* pnb  = (const float*)d_in[9];
    const float* mW1  = (const float*)d_in[10];
    const float* mb1  = (const float*)d_in[11];
    const float* mlng = (const float*)d_in[12];
    const float* mlnb = (const float*)d_in[13];
    const float* mW2  = (const float*)d_in[14];
    const float* mb2  = (const float*)d_in[15];

    const int N = in_sizes[0] / D;

    const size_t smemA = (size_t)(32 * 512 + 32 * 1024 + 32 * 128) * sizeof(float); // 208 KB
    const size_t smemC = (size_t)( 8 * 512 +  8 * 1024 + 32 * 128) * sizeof(float); //  64 KB
    cudaFuncSetAttribute(gemm_ln_kernel<0, 32>,
                         cudaFuncAttributeMaxDynamicSharedMemorySize, (int)smemA);
    cudaFuncSetAttribute(gemm_ln_kernel<1, 8>,
                         cudaFuncAttributeMaxDynamicSharedMemorySize, (int)smemC);

    // Phase A: gate scores for every row
    gemm_ln_kernel<0, 32><<<(N + 31) / 32, 256, smemA>>>(
        x, gW1, gb1, glng, glnb, gW2, gb2, N);

    // Phase B: segment boundaries
    segoff_kernel<<<1, 512>>>(ids, N);

    // Phase C: segment softmax + weighted pooling
    segpool_kernel<<<B, 256>>>(x, N);

    // Phase D: LN on pooled
    poolln_kernel<<<B, 256>>>(png, pnb);

    // Phase E: classifier hidden layer (reads g_pn internally, writes g_z)
    gemm_ln_kernel<1, 8><<<B / 8, 256, smemC>>>(
        x /*unused*/, mW1, mb1, mlng, mlnb, gW2 /*unused*/, gb2 /*unused*/, B);

    // Phase F: logits
    logits_kernel<<<B, 256>>>(mW2, mb2, (float*)d_out);
}

// round 3
// speedup vs baseline: 1.0009x; 1.0009x over previous
#include <cuda_runtime.h>

#define EPS 1e-5f

static constexpr int D    = 512;
static constexpr int COLS = 1024;   // 2*D and H (both 1024)
static constexpr int B    = 256;
static constexpr int OUTC = 250;

// ---------------- scratch (device globals; no allocation allowed) ----------------
__device__ float g_gate[100352];
__device__ int   g_segoff[257];
__device__ float g_pooled[B * D];
__device__ float g_pn[B * D];
__device__ float g_z[B * COLS];

// =====================================================================
// Fused GEMM (+bias) -> LayerNorm -> ReLU -> (MODE 0: dot with W2 -> g_gate,
//                                            MODE 1: store -> g_z)
// A is [M, 512] row-major, W is [1024, 512] row-major (we compute A @ W^T).
// =====================================================================
template<int MODE, int BM>
__global__ __launch_bounds__(256) void gemm_ln_kernel(
    const float* __restrict__ A, const float* __restrict__ W,
    const float* __restrict__ bias, const float* __restrict__ lng,
    const float* __restrict__ lnb, const float* __restrict__ W2,
    const float* __restrict__ b2, int M)
{
    constexpr int K  = 512;
    constexpr int BK = 32;
    constexpr int BN = 128;
    constexpr int TM = BM / 8;      // rows per thread (ty in 0..7)

    extern __shared__ float smem[];
    float* sx = smem;                 // [BM][K]
    float* sy = sx + BM * K;          // [BM][COLS]
    float* sw = sy + BM * COLS;       // [BK][BN] (transposed W chunk, swizzled)

    const int tid  = threadIdx.x;
    const int row0 = blockIdx.x * BM;
    const float* Ap = (MODE == 0) ? A : (const float*)g_pn;

    // ---- load x tile (BM*K floats) ----
    {
        const float4* src = (const float4*)Ap;
        float4* dst = (float4*)sx;
        const int nf4  = BM * K / 4;
        const int base = row0 * (K / 4);
        for (int i = tid; i < nf4; i += 256) dst[i] = src[base + i];
    }

    const int tx = tid & 31;   // 32 col-groups of 4 cols = 128 cols
    const int ty = tid >> 5;   // 8 row-groups of TM rows

    // ---- GEMM over 8 column chunks of 128 ----
    for (int cb = 0; cb < COLS; cb += BN) {
        float acc[TM][4];
        #pragma unroll
        for (int i = 0; i < TM; ++i) {
            #pragma unroll
            for (int j = 0; j < 4; ++j) acc[i][j] = 0.f;
        }

        for (int k0 = 0; k0 < K; k0 += BK) {
            __syncthreads();
            // stage W chunk transposed: logical sw[k][col], k in [0,32), col in [0,128)
            // XOR swizzle on 4-col groups by (k>>2): conflict-free stores AND reads.
            #pragma unroll
            for (int it = 0; it < 4; ++it) {
                int f   = tid + 256 * it;     // 0..1023 float4s
                int col = f >> 3;             // 0..127
                int kq  = f & 7;              // k-quad 0..7 (k = 4*kq + j)
                float4 v = *(const float4*)(W + (size_t)(cb + col) * K + k0 + 4 * kq);
                int p = (((col >> 2) ^ kq) << 2) + (col & 3);   // swizzled in-row pos
                sw[(4 * kq + 0) * BN + p] = v.x;
                sw[(4 * kq + 1) * BN + p] = v.y;
                sw[(4 * kq + 2) * BN + p] = v.z;
                sw[(4 * kq + 3) * BN + p] = v.w;
            }
            __syncthreads();

            const float4* swv = (const float4*)sw;
            #pragma unroll
            for (int kq = 0; kq < BK / 4; ++kq) {
                float4 a[TM];
                #pragma unroll
                for (int i = 0; i < TM; ++i)
                    a[i] = *(const float4*)(sx + (TM * ty + i) * K + k0 + 4 * kq);
                #pragma unroll
                for (int kk = 0; kk < 4; ++kk) {
                    float4 bv = swv[(4 * kq + kk) * (BN / 4) + (tx ^ kq)];
                    #pragma unroll
                    for (int i = 0; i < TM; ++i) {
                        float av = (kk == 0) ? a[i].x : (kk == 1) ? a[i].y
                                 : (kk == 2) ? a[i].z : a[i].w;
                        acc[i][0] += av * bv.x;
                        acc[i][1] += av * bv.y;
                        acc[i][2] += av * bv.z;
                        acc[i][3] += av * bv.w;
                    }
                }
            }
        }

        // write chunk (+bias) into sy
        float4 bb = *(const float4*)(bias + cb + 4 * tx);
        #pragma unroll
        for (int i = 0; i < TM; ++i) {
            float4 o;
            o.x = acc[i][0] + bb.x; o.y = acc[i][1] + bb.y;
            o.z = acc[i][2] + bb.z; o.w = acc[i][3] + bb.w;
            *(float4*)(sy + (TM * ty + i) * COLS + cb + 4 * tx) = o;
        }
    }
    __syncthreads();

    // ---- LayerNorm + ReLU (+ gate dot) ; one warp per row ----
    const int lane = tid & 31, warp = tid >> 5;
    for (int r = warp; r < BM; r += 8) {
        const float* yr = sy + r * COLS;
        float s1 = 0.f, s2 = 0.f;
        for (int c = lane; c < COLS; c += 32) { float v = yr[c]; s1 += v; s2 += v * v; }
        #pragma unroll
        for (int o = 16; o > 0; o >>= 1) {
            s1 += __shfl_xor_sync(0xffffffffu, s1, o);
            s2 += __shfl_xor_sync(0xffffffffu, s2, o);
        }
        float mean = s1 * (1.f / COLS);
        float var  = fmaxf(s2 * (1.f / COLS) - mean * mean, 0.f);
        float rstd = rsqrtf(var + EPS);
        if constexpr (MODE == 0) {
            float gsum = 0.f;
            for (int c = lane; c < COLS; c += 32) {
                float v = (yr[c] - mean) * rstd * lng[c] + lnb[c];
                gsum += fmaxf(v, 0.f) * W2[c];
            }
            #pragma unroll
            for (int o = 16; o > 0; o >>= 1)
                gsum += __shfl_xor_sync(0xffffffffu, gsum, o);
            if (lane == 0) g_gate[row0 + r] = gsum + b2[0];
        } else {
            for (int c = lane; c < COLS; c += 32) {
                float v = (yr[c] - mean) * rstd * lng[c] + lnb[c];
                g_z[(size_t)(row0 + r) * COLS + c] = fmaxf(v, 0.f);
            }
        }
    }
}

// =====================================================================
// Segment offsets via binary search (batch_ids sorted ascending)
// =====================================================================
__global__ void segoff_kernel(const int* __restrict__ ids, int N)
{
    int b = threadIdx.x;
    if (b > B) return;
    int lo = 0, hi = N;
    while (lo < hi) { int mid = (lo + hi) >> 1; if (ids[mid] < b) lo = mid + 1; else hi = mid; }
    g_segoff[b] = lo;
}

// =====================================================================
// Per-segment softmax + weighted pooling: g_pooled[b][:] = sum_i w_i * x[i][:]
// =====================================================================
__global__ __launch_bounds__(256) void segpool_kernel(const float* __restrict__ x, int N)
{
    __shared__ float red[32];
    __shared__ float sm_w[256];
    __shared__ float s_m, s_inv;

    const int b = blockIdx.x;
    const int tid = threadIdx.x;
    const int lane = tid & 31, warp = tid >> 5;
    const int s = g_segoff[b], e = g_segoff[b + 1];

    // ---- segment max ----
    float m = -3.402823466e38f;
    for (int i = s + tid; i < e; i += 256) m = fmaxf(m, g_gate[i]);
    #pragma unroll
    for (int o = 16; o > 0; o >>= 1) m = fmaxf(m, __shfl_xor_sync(0xffffffffu, m, o));
    if (lane == 0) red[warp] = m;
    __syncthreads();
    if (tid < 32) {
        float v = (tid < 8) ? red[tid] : -3.402823466e38f;
        #pragma unroll
        for (int o = 4; o > 0; o >>= 1) v = fmaxf(v, __shfl_xor_sync(0xffffffffu, v, o));
        if (tid == 0) s_m = v;
    }
    __syncthreads();
    m = s_m;

    // ---- sum of exp ----
    float ssum = 0.f;
    for (int i = s + tid; i < e; i += 256) ssum += expf(g_gate[i] - m);
    #pragma unroll
    for (int o = 16; o > 0; o >>= 1) ssum += __shfl_xor_sync(0xffffffffu, ssum, o);
    __syncthreads();
    if (lane == 0) red[warp] = ssum;
    __syncthreads();
    if (tid < 32) {
        float v = (tid < 8) ? red[tid] : 0.f;
        #pragma unroll
        for (int o = 4; o > 0; o >>= 1) v += __shfl_xor_sync(0xffffffffu, v, o);
        if (tid == 0) s_inv = (v > 0.f) ? (1.f / v) : 0.f;
    }
    __syncthreads();
    const float inv = s_inv;

    // ---- pooled: each thread owns 2 columns ----
    float2 accp = make_float2(0.f, 0.f);
    for (int base = s; base < e; base += 256) {
        int i = base + tid;
        sm_w[tid] = (i < e) ? expf(g_gate[i] - m) * inv : 0.f;
        __syncthreads();
        int cnt = min(256, e - base);
        #pragma unroll 4
        for (int r = 0; r < cnt; ++r) {
            float w = sm_w[r];
            float2 xv = *(const float2*)(x + (size_t)(base + r) * D + 2 * tid);
            accp.x += w * xv.x;
            accp.y += w * xv.y;
        }
        __syncthreads();
    }
    *(float2*)(g_pooled + b * D + 2 * tid) = accp;
}

// =====================================================================
// LayerNorm on pooled rows -> g_pn
// =====================================================================
__global__ __launch_bounds__(256) void poolln_kernel(const float* __restrict__ g,
                                                     const float* __restrict__ bt)
{
    __shared__ float red[64];
    __shared__ float s_mean, s_rstd;
    const int b = blockIdx.x, tid = threadIdx.x;
    const int lane = tid & 31, warp = tid >> 5;

    float v0 = g_pooled[b * D + tid];
    float v1 = g_pooled[b * D + 256 + tid];
    float s1 = v0 + v1, s2 = v0 * v0 + v1 * v1;
    #pragma unroll
    for (int o = 16; o > 0; o >>= 1) {
        s1 += __shfl_xor_sync(0xffffffffu, s1, o);
        s2 += __shfl_xor_sync(0xffffffffu, s2, o);
    }
    if (lane == 0) { red[warp] = s1; red[8 + warp] = s2; }
    __syncthreads();
    if (tid < 32) {
        float a1 = (tid < 8) ? red[tid] : 0.f;
        float a2 = (tid < 8) ? red[8 + tid] : 0.f;
        #pragma unroll
        for (int o = 4; o > 0; o >>= 1) {
            a1 += __shfl_xor_sync(0xffffffffu, a1, o);
            a2 += __shfl_xor_sync(0xffffffffu, a2, o);
        }
        if (tid == 0) {
            float mean = a1 * (1.f / D);
            float var  = fmaxf(a2 * (1.f / D) - mean * mean, 0.f);
            s_mean = mean;
            s_rstd = rsqrtf(var + EPS);
        }
    }
    __syncthreads();
    float mean = s_mean, rstd = s_rstd;
    g_pn[b * D + tid]       = (v0 - mean) * rstd * g[tid]       + bt[tid];
    g_pn[b * D + 256 + tid] = (v1 - mean) * rstd * g[tid + 256] + bt[tid + 256];
}

// =====================================================================
// logits = z @ mW2^T + mb2   (one CTA per batch row, z row cached in smem)
// =====================================================================
__global__ __launch_bounds__(256) void logits_kernel(const float* __restrict__ W2,
                                                     const float* __restrict__ b2,
                                                     float* __restrict__ out)
{
    __shared__ float sz[COLS];
    const int b = blockIdx.x, tid = threadIdx.x;
    for (int i = tid; i < COLS; i += 256) sz[i] = g_z[(size_t)b * COLS + i];
    __syncthreads();
    if (tid < OUTC) {
        const float4* wr = (const float4*)(W2 + (size_t)tid * COLS);
        const float4* zr = (const float4*)sz;
        float acc = 0.f;
        #pragma unroll 4
        for (int k = 0; k < COLS / 4; ++k) {
            float4 w = wr[k], zz = zr[k];
            acc += w.x * zz.x + w.y * zz.y + w.z * zz.z + w.w * zz.w;
        }
        out[b * OUTC + tid] = acc + b2[tid];
    }
}

// =====================================================================
extern "C" void kernel_launch(void* const* d_in, const int* in_sizes, int n_in,
                              void* d_out, int out_size)
{
    const float* x    = (const float*)d_in[0];
    const int*   ids  = (const int*)  d_in[1];
    const float* gW1  = (const float*)d_in[2];
    const float* gb1  = (const float*)d_in[3];
    const float* glng = (const float*)d_in[4];
    const float* glnb = (const float*)d_in[5];
    const float* gW2  = (const float*)d_in[6];
    const float* gb2  = (const float*)d_in[7];
    const float* png  = (const float*)d_in[8];
    const float* pnb  = (const float*)d_in[9];
    const float* mW1  = (const float*)d_in[10];
    const float* mb1  = (const float*)d_in[11];
    const float* mlng = (const float*)d_in[12];
    const float* mlnb = (const float*)d_in[13];
    const float* mW2  = (const float*)d_in[14];
    const float* mb2  = (const float*)d_in[15];

    const int N = in_sizes[0] / D;

    const size_t smemA = (size_t)(32 * 512 + 32 * 1024 + 32 * 128) * sizeof(float); // 208 KB
    const size_t smemC = (size_t)( 8 * 512 +  8 * 1024 + 32 * 128) * sizeof(float); //  64 KB
    cudaFuncSetAttribute(gemm_ln_kernel<0, 32>,
                         cudaFuncAttributeMaxDynamicSharedMemorySize, (int)smemA);
    cudaFuncSetAttribute(gemm_ln_kernel<1, 8>,
                         cudaFuncAttributeMaxDynamicSharedMemorySize, (int)smemC);

    // Phase A: gate scores for every row
    gemm_ln_kernel<0, 32><<<(N + 31) / 32, 256, smemA>>>(
        x, gW1, gb1, glng, glnb, gW2, gb2, N);

    // Phase B: segment boundaries
    segoff_kernel<<<1, 512>>>(ids, N);

    // Phase C: segment softmax + weighted pooling
    segpool_kernel<<<B, 256>>>(x, N);

    // Phase D: LN on pooled
    poolln_kernel<<<B, 256>>>(png, pnb);

    // Phase E: classifier hidden layer (reads g_pn internally, writes g_z)
    gemm_ln_kernel<1, 8><<<B / 8, 256, smemC>>>(
        x /*unused*/, mW1, mb1, mlng, mlnb, gW2 /*unused*/, gb2 /*unused*/, B);

    // Phase F: logits
    logits_kernel<<<B, 256>>>(mW2, mb2, (float*)d_out);
}

// round 7
// speedup vs baseline: 3.0286x; 3.0259x over previous
#include <cuda_runtime.h>
#include <cuda_bf16.h>
#include <mma.h>
#include <cstdint>
using namespace nvcuda;

#define EPS 1e-5f
static constexpr int D = 512, COLS = 1024, B = 256, OUTC = 250, MAXT = 784;

__device__ float g_gate[MAXT * 128];
__device__ int   g_segoff[257];
__device__ float g_pooled[B * D];
__device__ float g_pn[B * D];
__device__ float g_z[B * COLS];
__device__ float g_y[(size_t)MAXT * 128 * 1024];
__device__ __align__(16) __nv_bfloat16 g_xh[(size_t)MAXT * 128 * 512];
__device__ __align__(16) __nv_bfloat16 g_xl[(size_t)MAXT * 128 * 512];
__device__ __align__(16) __nv_bfloat16 g_wh[1024 * 512];
__device__ __align__(16) __nv_bfloat16 g_wl[1024 * 512];

__device__ __forceinline__ uint32_t smem_u32(const void* p) {
    uint32_t a;
    asm("{ .reg .u64 t; cvta.to.shared.u64 t, %1; cvt.u32.u64 %0, t; }" : "=r"(a) : "l"(p));
    return a;
}
__device__ __forceinline__ void cp16(uint32_t d, const void* s) {
    asm volatile("cp.async.cg.shared.global [%0], [%1], 16;" :: "r"(d), "l"(s) : "memory");
}
#define CP_COMMIT() asm volatile("cp.async.commit_group;" ::: "memory")
#define CP_WAIT1()  asm volatile("cp.async.wait_group 1;" ::: "memory")
#define CP_WAIT0()  asm volatile("cp.async.wait_group 0;" ::: "memory")

__device__ __forceinline__ void split8(const float* a, uint4& hp, uint4& lp) {
    uint32_t h[4], l[4];
    #pragma unroll
    for (int i = 0; i < 4; ++i) {
        __nv_bfloat16 h0 = __float2bfloat16(a[2*i]), h1 = __float2bfloat16(a[2*i+1]);
        __nv_bfloat16 l0 = __float2bfloat16(a[2*i]   - __bfloat162float(h0));
        __nv_bfloat16 l1 = __float2bfloat16(a[2*i+1] - __bfloat162float(h1));
        h[i] = (uint32_t)*(unsigned short*)&h0 | ((uint32_t)*(unsigned short*)&h1 << 16);
        l[i] = (uint32_t)*(unsigned short*)&l0 | ((uint32_t)*(unsigned short*)&l1 << 16);
    }
    hp = make_uint4(h[0], h[1], h[2], h[3]); lp = make_uint4(l[0], l[1], l[2], l[3]);
}

// ---------- prep: fp32 -> bf16 hi/lo, plain row-major ----------
__global__ __launch_bounds__(256) void prep_w(const float* __restrict__ w) {
    size_t id = (size_t)blockIdx.x * 256 + threadIdx.x;   // 65536 (8 elems each)
    float a[8];
    *(float4*)a       = *(const float4*)(w + id * 8);
    *(float4*)(a + 4) = *(const float4*)(w + id * 8 + 4);
    uint4 hp, lp; split8(a, hp, lp);
    ((uint4*)g_wh)[id] = hp; ((uint4*)g_wl)[id] = lp;
}
__global__ __launch_bounds__(256) void prep_x(const float* __restrict__ x, int n) {
    size_t id = (size_t)blockIdx.x * 256 + threadIdx.x;   // padN*64
    int row = (int)(id >> 6);
    float a[8] = {0, 0, 0, 0, 0, 0, 0, 0};
    if (row < n) {
        *(float4*)a       = *(const float4*)(x + id * 8);
        *(float4*)(a + 4) = *(const float4*)(x + id * 8 + 4);
    }
    uint4 hp, lp; split8(a, hp, lp);
    ((uint4*)g_xh)[id] = hp; ((uint4*)g_xl)[id] = lp;
}

// ---------- phase A GEMM: y = x @ W^T  (bf16-split, wmma) ----------
// CTA: 128 rows x 128 cols, 8 warps (4m x 2n), warp tile 32x64. K chunks of 32.
static constexpr int SSTRIDE = 40;                        // bf16 elems per smem row
static constexpr uint32_t MATB = 128 * SSTRIDE * 2;       // 10240 bytes per matrix
static constexpr uint32_t BUFB = 4 * MATB;                // 40960 per buffer
static constexpr uint32_t SMT  = 2 * BUFB;                // 81920 total

__global__ __launch_bounds__(256) void gemm_k() {
    extern __shared__ char smem[];
    const int tid = threadIdx.x, wid = tid >> 5;
    const int cb = blockIdx.x, tile = blockIdx.y;         // col-block, row-tile
    const int wm = wid & 3, wn = wid >> 2;
    const uint32_t sb = smem_u32(smem);

    const __nv_bfloat16* baseA[2] = {g_xh + (size_t)tile * 128 * 512,
                                     g_xl + (size_t)tile * 128 * 512};
    const __nv_bfloat16* baseB[2] = {g_wh + (size_t)cb * 128 * 512,
                                     g_wl + (size_t)cb * 128 * 512};

    auto stage = [&](int kc, int buf) {
        uint32_t d0 = sb + buf * BUFB;
        #pragma unroll
        for (int it = 0; it < 8; ++it) {
            int t = tid + it * 256;                        // 0..2047
            int mat = t >> 9, r = (t & 511) >> 2, seg = t & 3;
            const __nv_bfloat16* src =
                ((mat & 2) ? baseB[mat & 1] : baseA[mat & 1]) +
                (size_t)r * 512 + kc * 32 + seg * 8;
            cp16(d0 + mat * MATB + (uint32_t)(r * SSTRIDE + seg * 8) * 2, src);
        }
    };

    wmma::fragment<wmma::accumulator, 16, 16, 16, float> acc[2][4];
    #pragma unroll
    for (int mt = 0; mt < 2; ++mt)
        #pragma unroll
        for (int nt = 0; nt < 4; ++nt) wmma::fill_fragment(acc[mt][nt], 0.f);

    stage(0, 0); CP_COMMIT();
    for (int kc = 0; kc < 16; ++kc) {
        if (kc < 15) { stage(kc + 1, (kc + 1) & 1); CP_COMMIT(); CP_WAIT1(); }
        else         { CP_WAIT0(); }
        __syncthreads();
        const __nv_bfloat16* s0 = (const __nv_bfloat16*)(smem + (kc & 1) * BUFB);
        const __nv_bfloat16* sAh = s0;
        const __nv_bfloat16* sAl = s0 + 128 * SSTRIDE;
        const __nv_bfloat16* sBh = s0 + 2 * 128 * SSTRIDE;
        const __nv_bfloat16* sBl = s0 + 3 * 128 * SSTRIDE;
        #pragma unroll
        for (int ks = 0; ks < 2; ++ks) {
            wmma::fragment<wmma::matrix_a, 16, 16, 16, __nv_bfloat16, wmma::row_major> ah[2], al[2];
            wmma::fragment<wmma::matrix_b, 16, 16, 16, __nv_bfloat16, wmma::col_major> bh[4], bl[4];
            #pragma unroll
            for (int mt = 0; mt < 2; ++mt) {
                int ro = (wm * 32 + mt * 16) * SSTRIDE + ks * 16;
                wmma::load_matrix_sync(ah[mt], sAh + ro, SSTRIDE);
                wmma::load_matrix_sync(al[mt], sAl + ro, SSTRIDE);
            }
            #pragma unroll
            for (int nt = 0; nt < 4; ++nt) {
                int co = (wn * 64 + nt * 16) * SSTRIDE + ks * 16;
                wmma::load_matrix_sync(bh[nt], sBh + co, SSTRIDE);
                wmma::load_matrix_sync(bl[nt], sBl + co, SSTRIDE);
            }
            #pragma unroll
            for (int mt = 0; mt < 2; ++mt)
                #pragma unroll
                for (int nt = 0; nt < 4; ++nt) {
                    wmma::mma_sync(acc[mt][nt], ah[mt], bh[nt], acc[mt][nt]);
                    wmma::mma_sync(acc[mt][nt], al[mt], bh[nt], acc[mt][nt]);
                    wmma::mma_sync(acc[mt][nt], ah[mt], bl[nt], acc[mt][nt]);
                }
        }
        __syncthreads();
    }
    #pragma unroll
    for (int mt = 0; mt < 2; ++mt)
        #pragma unroll
        for (int nt = 0; nt < 4; ++nt) {
            size_t row0 = (size_t)tile * 128 + wm * 32 + mt * 16;
            int col0 = cb * 128 + wn * 64 + nt * 16;
            wmma::store_matrix_sync(g_y + row0 * 1024 + col0, acc[mt][nt], 1024,
                                    wmma::mem_row_major);
        }
}

// ---------- LN + ReLU + gate dot (one warp per row) ----------
__global__ __launch_bounds__(256) void ln_gate_k(
    const float* __restrict__ bias, const float* __restrict__ lng,
    const float* __restrict__ lnb, const float* __restrict__ W2,
    const float* __restrict__ b2, int N)
{
    const int row = blockIdx.x * 8 + (threadIdx.x >> 5);
    if (row >= N) return;
    const int lane = threadIdx.x & 31;
    const float4* yr = (const float4*)(g_y + (size_t)row * 1024);
    const float4* b4 = (const float4*)bias;
    float4 v[8]; float s1 = 0.f, s2 = 0.f;
    #pragma unroll
    for (int j = 0; j < 8; ++j) {
        int i = j * 32 + lane;
        float4 t = yr[i], bb = b4[i];
        t.x += bb.x; t.y += bb.y; t.z += bb.z; t.w += bb.w;
        v[j] = t;
        s1 += t.x + t.y + t.z + t.w;
        s2 += t.x * t.x + t.y * t.y + t.z * t.z + t.w * t.w;
    }
    #pragma unroll
    for (int o = 16; o > 0; o >>= 1) {
        s1 += __shfl_xor_sync(~0u, s1, o);
        s2 += __shfl_xor_sync(~0u, s2, o);
    }
    float mean = s1 * (1.f / 1024.f);
    float rstd = rsqrtf(fmaxf(s2 * (1.f / 1024.f) - mean * mean, 0.f) + EPS);
    float gd = 0.f;
    #pragma unroll
    for (int j = 0; j < 8; ++j) {
        int i = j * 32 + lane;
        float4 g = ((const float4*)lng)[i], lb = ((const float4*)lnb)[i],
               w = ((const float4*)W2)[i];
        float t;
        t = (v[j].x - mean) * rstd * g.x + lb.x; gd += fmaxf(t, 0.f) * w.x;
        t = (v[j].y - mean) * rstd * g.y + lb.y; gd += fmaxf(t, 0.f) * w.y;
        t = (v[j].z - mean) * rstd * g.z + lb.z; gd += fmaxf(t, 0.f) * w.z;
        t = (v[j].w - mean) * rstd * g.w + lb.w; gd += fmaxf(t, 0.f) * w.w;
    }
    #pragma unroll
    for (int o = 16; o > 0; o >>= 1) gd += __shfl_xor_sync(~0u, gd, o);
    if (lane == 0) g_gate[row] = gd + b2[0];
}

// ---------- tail (proven) ----------
__global__ void segoff_k(const int* __restrict__ ids, int N) {
    int b = threadIdx.x; if (b > B) return;
    int lo = 0, hi = N;
    while (lo < hi) { int m = (lo + hi) >> 1; if (ids[m] < b) lo = m + 1; else hi = m; }
    g_segoff[b] = lo;
}
__global__ __launch_bounds__(256) void segpool_k(const float* __restrict__ x) {
    __shared__ float red[32], sw[256], s_m, s_i;
    const int b = blockIdx.x, tid = threadIdx.x, lane = tid & 31, warp = tid >> 5;
    const int s = g_segoff[b], e = g_segoff[b + 1];
    float m = -3.4e38f;
    for (int i = s + tid; i < e; i += 256) m = fmaxf(m, g_gate[i]);
    for (int o = 16; o > 0; o >>= 1) m = fmaxf(m, __shfl_xor_sync(~0u, m, o));
    if (lane == 0) red[warp] = m;
    __syncthreads();
    if (tid < 32) {
        float v = (tid < 8) ? red[tid] : -3.4e38f;
        for (int o = 4; o > 0; o >>= 1) v = fmaxf(v, __shfl_xor_sync(~0u, v, o));
        if (tid == 0) s_m = v;
    }
    __syncthreads(); m = s_m;
    float ss = 0.f;
    for (int i = s + tid; i < e; i += 256) ss += expf(g_gate[i] - m);
    for (int o = 16; o > 0; o >>= 1) ss += __shfl_xor_sync(~0u, ss, o);
    __syncthreads();
    if (lane == 0) red[warp] = ss;
    __syncthreads();
    if (tid < 32) {
        float v = (tid < 8) ? red[tid] : 0.f;
        for (int o = 4; o > 0; o >>= 1) v += __shfl_xor_sync(~0u, v, o);
        if (tid == 0) s_i = (v > 0.f) ? 1.f / v : 0.f;
    }
    __syncthreads();
    const float inv = s_i;
    float2 acc = make_float2(0.f, 0.f);
    for (int base = s; base < e; base += 256) {
        int i = base + tid;
        sw[tid] = (i < e) ? expf(g_gate[i] - m) * inv : 0.f;
        __syncthreads();
        int cnt = min(256, e - base);
        #pragma unroll 4
        for (int r = 0; r < cnt; ++r) {
            float w = sw[r];
            float2 xv = *(const float2*)(x + (size_t)(base + r) * D + 2 * tid);
            acc.x += w * xv.x; acc.y += w * xv.y;
        }
        __syncthreads();
    }
    *(float2*)(g_pooled + b * D + 2 * tid) = acc;
}
__global__ __launch_bounds__(256) void poolln_k(const float* __restrict__ g, const float* __restrict__ bt) {
    __shared__ float red[64]; __shared__ float sm, sr;
    const int b = blockIdx.x, tid = threadIdx.x, lane = tid & 31, warp = tid >> 5;
    float v0 = g_pooled[b * D + tid], v1 = g_pooled[b * D + 256 + tid];
    float s1 = v0 + v1, s2 = v0 * v0 + v1 * v1;
    for (int o = 16; o > 0; o >>= 1) { s1 += __shfl_xor_sync(~0u, s1, o); s2 += __shfl_xor_sync(~0u, s2, o); }
    if (lane == 0) { red[warp] = s1; red[8 + warp] = s2; }
    __syncthreads();
    if (tid < 32) {
        float a1 = (tid < 8) ? red[tid] : 0.f, a2 = (tid < 8) ? red[8 + tid] : 0.f;
        for (int o = 4; o > 0; o >>= 1) { a1 += __shfl_xor_sync(~0u, a1, o); a2 += __shfl_xor_sync(~0u, a2, o); }
        if (tid == 0) {
            float mn = a1 * (1.f / D);
            sm = mn; sr = rsqrtf(fmaxf(a2 * (1.f / D) - mn * mn, 0.f) + EPS);
        }
    }
    __syncthreads();
    g_pn[b * D + tid]       = (v0 - sm) * sr * g[tid]       + bt[tid];
    g_pn[b * D + 256 + tid] = (v1 - sm) * sr * g[tid + 256] + bt[tid + 256];
}
__global__ __launch_bounds__(256) void cls_hidden_k(const float* __restrict__ W1, const float* __restrict__ b1,
                                                    const float* __restrict__ g, const float* __restrict__ bt) {
    __shared__ float sp[512]; __shared__ float red[64]; __shared__ float sm, sr;
    const int b = blockIdx.x, tid = threadIdx.x, lane = tid & 31, warp = tid >> 5;
    for (int i = tid; i < 512; i += 256) sp[i] = g_pn[b * D + i];
    __syncthreads();
    float v[4]; float s1 = 0.f, s2 = 0.f;
    #pragma unroll
    for (int cc = 0; cc < 4; ++cc) {
        int c = tid * 4 + cc;
        const float4* w = (const float4*)(W1 + (size_t)c * 512);
        const float4* p = (const float4*)sp;
        float a = b1[c];
        #pragma unroll 4
        for (int k = 0; k < 128; ++k) {
            float4 wv = w[k], pv = p[k];
            a += wv.x * pv.x + wv.y * pv.y + wv.z * pv.z + wv.w * pv.w;
        }
        v[cc] = a; s1 += a; s2 += a * a;
    }
    for (int o = 16; o > 0; o >>= 1) { s1 += __shfl_xor_sync(~0u, s1, o); s2 += __shfl_xor_sync(~0u, s2, o); }
    if (lane == 0) { red[warp] = s1; red[8 + warp] = s2; }
    __syncthreads();
    if (tid < 32) {
        float a1 = (tid < 8) ? red[tid] : 0.f, a2 = (tid < 8) ? red[8 + tid] : 0.f;
        for (int o = 4; o > 0; o >>= 1) { a1 += __shfl_xor_sync(~0u, a1, o); a2 += __shfl_xor_sync(~0u, a2, o); }
        if (tid == 0) {
            float mn = a1 * (1.f / COLS);
            sm = mn; sr = rsqrtf(fmaxf(a2 * (1.f / COLS) - mn * mn, 0.f) + EPS);
        }
    }
    __syncthreads();
    #pragma unroll
    for (int cc = 0; cc < 4; ++cc) {
        int c = tid * 4 + cc;
        g_z[(size_t)b * COLS + c] = fmaxf((v[cc] - sm) * sr * g[c] + bt[c], 0.f);
    }
}
__global__ __launch_bounds__(256) void logits_k(const float* __restrict__ W2, const float* __restrict__ b2,
                                                float* __restrict__ out) {
    __shared__ float sz[COLS];
    const int b = blockIdx.x, tid = threadIdx.x;
    for (int i = tid; i < COLS; i += 256) sz[i] = g_z[(size_t)b * COLS + i];
    __syncthreads();
    if (tid < OUTC) {
        const float4* wr = (const float4*)(W2 + (size_t)tid * COLS);
        const float4* zr = (const float4*)sz;
        float acc = 0.f;
        #pragma unroll 4
        for (int k = 0; k < COLS / 4; ++k) {
            float4 w = wr[k], z = zr[k];
            acc += w.x * z.x + w.y * z.y + w.z * z.z + w.w * z.w;
        }
        out[b * OUTC + tid] = acc + b2[tid];
    }
}

extern "C" void kernel_launch(void* const* d_in, const int* in_sizes, int n_in,
                              void* d_out, int out_size) {
    const float* x    = (const float*)d_in[0];
    const int*   ids  = (const int*)  d_in[1];
    const float* gW1  = (const float*)d_in[2];
    const float* gb1  = (const float*)d_in[3];
    const float* glng = (const float*)d_in[4];
    const float* glnb = (const float*)d_in[5];
    const float* gW2  = (const float*)d_in[6];
    const float* gb2  = (const float*)d_in[7];
    const float* png  = (const float*)d_in[8];
    const float* pnb  = (const float*)d_in[9];
    const float* mW1  = (const float*)d_in[10];
    const float* mb1  = (const float*)d_in[11];
    const float* mlng = (const float*)d_in[12];
    const float* mlnb = (const float*)d_in[13];
    const float* mW2  = (const float*)d_in[14];
    const float* mb2  = (const float*)d_in[15];
    const int N = in_sizes[0] / D;
    const int tiles = (N + 127) / 128;

    cudaFuncSetAttribute(gemm_k, cudaFuncAttributeMaxDynamicSharedMemorySize, SMT);

    prep_w<<<256, 256>>>(gW1);
    prep_x<<<tiles * 32, 256>>>(x, N);
    gemm_k<<<dim3(8, tiles), 256, SMT>>>();
    ln_gate_k<<<(N + 7) / 8, 256>>>(gb1, glng, glnb, gW2, gb2, N);
    segoff_k<<<1, 512>>>(ids, N);
    segpool_k<<<B, 256>>>(x);
    poolln_k<<<B, 256>>>(png, pnb);
    cls_hidden_k<<<B, 256>>>(mW1, mb1, mlng, mlnb);
    logits_k<<<B, 256>>>(mW2, mb2, (float*)d_out);
}